// round 16
// baseline (speedup 1.0000x reference)
#include <cuda_runtime.h>
#include <cuda_fp16.h>
#include <cstdint>

#define BATCH   64
#define CDIM    256
#define TDIM    2048

#define THREADS 512
#define BK      32                      // k floats per stage
#define NSTEPS  (TDIM / BK)             // 64
#define ROWB    80                      // fp16 row: 64B data + 16B pad (conflict-free, per R6)
#define SLOT_BYTES (CDIM * ROWB)        // 20480

__device__ __forceinline__ uint32_t smem_u32(const void* p) {
    uint32_t a;
    asm("{ .reg .u64 t; cvta.to.shared.u64 t, %1; cvt.u32.u64 %0, t; }"
        : "=r"(a) : "l"(p));
    return a;
}
__device__ __forceinline__ void ldsm_x4(uint32_t* r, uint32_t addr) {
    asm volatile("ldmatrix.sync.aligned.m8n8.x4.shared.b16 {%0,%1,%2,%3}, [%4];"
                 : "=r"(r[0]), "=r"(r[1]), "=r"(r[2]), "=r"(r[3]) : "r"(addr));
}
__device__ __forceinline__ void mma_f16(float* c, const uint32_t* a,
                                        uint32_t b0, uint32_t b1) {
    asm volatile(
        "mma.sync.aligned.m16n8k16.row.col.f32.f16.f16.f32 "
        "{%0,%1,%2,%3}, {%4,%5,%6,%7}, {%8,%9}, {%0,%1,%2,%3};"
        : "+f"(c[0]), "+f"(c[1]), "+f"(c[2]), "+f"(c[3])
        : "r"(a[0]), "r"(a[1]), "r"(a[2]), "r"(a[3]), "r"(b0), "r"(b1));
}

// ---------------------------------------------------------------------------
// Fully fused covariance kernel. 128 CTAs: blockIdx.x = b*2 + mhalf.
// Loads fp32 X directly (LDG->regs), converts to fp16, stages ONLY the
// 256-row B region in smem (A rows are a subset -> A frags read from it too).
// Row sums for means accumulate on the register data; reduced via shfl.
// D[128 x 256] per CTA, 16 warps (2x8), warp tile 64x32, m16n8k16.
// ---------------------------------------------------------------------------
__global__ void __launch_bounds__(THREADS, 1)
cov_fused_kernel(const float* __restrict__ X, float* __restrict__ out) {
    __shared__ float sm_rowsum[CDIM];
    __shared__ float sm_mean[CDIM];
    __shared__ __align__(16) char sm_buf[2][SLOT_BYTES];

    const int b    = blockIdx.x >> 1;
    const int row0 = (blockIdx.x & 1) * 128;
    const int tid  = threadIdx.x;
    const int wid  = tid >> 5;
    const int lane = tid & 31;
    const int g    = lane >> 2;
    const int tig  = lane & 3;
    const int wm   = wid >> 3;          // 0..1  (64-row half of this CTA's 128)
    const int wn   = wid & 7;           // 0..7  (32-col slab)

    const uint32_t slot_u32[2] = { smem_u32(sm_buf[0]), smem_u32(sm_buf[1]) };

    // --- loader mapping: 4 x (row, chunk) slots per thread, fixed all stages
    //     idx = tid + u*512 in [0,2048): row = idx>>3 (0..255), ch = idx&7.
    //     Each stage: thread reads float4 X[row][s*32 + ch*4 .. +3].
    const float* Xb = X + (size_t)b * CDIM * TDIM;
    uint32_t srcofs[4];                 // float offset within batch
    uint32_t stsoff[4];                 // byte offset within slot
    int      mrow[4];
#pragma unroll
    for (int u = 0; u < 4; u++) {
        int idx = tid + u * THREADS;
        int row = idx >> 3, ch = idx & 7;
        srcofs[u] = (uint32_t)(row * TDIM + ch * 4);
        stsoff[u] = (uint32_t)(row * ROWB + ch * 8);
        mrow[u]   = row;
    }
    float msum[4] = {0.f, 0.f, 0.f, 0.f};

    // --- ldmatrix base byte-offsets within a slot (A reads the B region!) ---
    uint32_t aoff[4], boff[2];
#pragma unroll
    for (int i = 0; i < 4; i++)
        aoff[i] = (uint32_t)((row0 + wm * 64 + i * 16 + (lane & 15)) * ROWB +
                             (lane >> 4) * 16);
#pragma unroll
    for (int jp = 0; jp < 2; jp++)
        boff[jp] = (uint32_t)((wn * 32 + jp * 16 + (lane & 15)) * ROWB +
                              (lane >> 4) * 16);

    float acc[4][4][4];
#pragma unroll
    for (int i = 0; i < 4; i++)
#pragma unroll
        for (int j = 0; j < 4; j++)
#pragma unroll
            for (int q = 0; q < 4; q++) acc[i][j][q] = 0.0f;

    // --- prologue: LDG stage 0 into registers ---
    float4 buf[4];
#pragma unroll
    for (int u = 0; u < 4; u++)
        buf[u] = __ldg(reinterpret_cast<const float4*>(Xb + srcofs[u]));

    for (int s = 0; s < NSTEPS; s++) {
        const uint32_t sb = slot_u32[s & 1];
        char* sbp = sm_buf[s & 1];

        // mean-accumulate + convert + store stage s (from registers)
#pragma unroll
        for (int u = 0; u < 4; u++) {
            float4 v = buf[u];
            msum[u] += (v.x + v.y) + (v.z + v.w);
            __half2 h01 = __floats2half2_rn(v.x, v.y);
            __half2 h23 = __floats2half2_rn(v.z, v.w);
            uint2 o;
            o.x = reinterpret_cast<uint32_t&>(h01);
            o.y = reinterpret_cast<uint32_t&>(h23);
            *reinterpret_cast<uint2*>(sbp + stsoff[u]) = o;
        }

        // prefetch stage s+1 into registers (hidden under barrier + MMAs)
        if (s + 1 < NSTEPS) {
#pragma unroll
            for (int u = 0; u < 4; u++)
                buf[u] = __ldg(reinterpret_cast<const float4*>(
                    Xb + srcofs[u] + (s + 1) * BK));
        }

        __syncthreads();   // stage s visible to all; also fences slot reuse

#pragma unroll
        for (int kk = 0; kk < 2; kk++) {
            const uint32_t ko = sb + kk * 32;        // 16 halves = 32B
            uint32_t a[4][4], br[2][4];
#pragma unroll
            for (int i = 0; i < 4; i++)   ldsm_x4(a[i],   ko + aoff[i]);
#pragma unroll
            for (int jp = 0; jp < 2; jp++) ldsm_x4(br[jp], ko + boff[jp]);
#pragma unroll
            for (int i = 0; i < 4; i++)
#pragma unroll
                for (int jp = 0; jp < 2; jp++) {
                    mma_f16(acc[i][2 * jp],     a[i], br[jp][0], br[jp][2]);
                    mma_f16(acc[i][2 * jp + 1], a[i], br[jp][1], br[jp][3]);
                }
        }
    }

    // --- deterministic mean reduction: 8 chunk-partials per row live in 8
    //     consecutive lanes of one warp; butterfly, lane (tid&7)==0 writes.
#pragma unroll
    for (int u = 0; u < 4; u++) {
        float v = msum[u];
        v += __shfl_xor_sync(0xffffffffu, v, 1);
        v += __shfl_xor_sync(0xffffffffu, v, 2);
        v += __shfl_xor_sync(0xffffffffu, v, 4);
        if ((tid & 7) == 0) sm_rowsum[mrow[u]] = v;
    }
    __syncthreads();
    if (tid < CDIM) sm_mean[tid] = sm_rowsum[tid] * (1.0f / TDIM);
    __syncthreads();

    // --- epilogue: cov = acc/T - m_r*m_c ---
    const float invT = 1.0f / TDIM;
    float* outB = out + (size_t)b * CDIM * CDIM;

#pragma unroll
    for (int i = 0; i < 4; i++) {
        const int r0 = row0 + wm * 64 + i * 16 + g;
        const int r1 = r0 + 8;
        const float mr0 = sm_mean[r0];
        const float mr1 = sm_mean[r1];
#pragma unroll
        for (int j = 0; j < 4; j++) {
            const int c = wn * 32 + j * 8 + 2 * tig;
            const float mc0 = sm_mean[c];
            const float mc1 = sm_mean[c + 1];
            float2 v0, v1;
            v0.x = acc[i][j][0] * invT - mr0 * mc0;
            v0.y = acc[i][j][1] * invT - mr0 * mc1;
            v1.x = acc[i][j][2] * invT - mr1 * mc0;
            v1.y = acc[i][j][3] * invT - mr1 * mc1;
            *reinterpret_cast<float2*>(outB + (size_t)r0 * CDIM + c) = v0;
            *reinterpret_cast<float2*>(outB + (size_t)r1 * CDIM + c) = v1;
        }
    }
}

// ---------------------------------------------------------------------------
extern "C" void kernel_launch(void* const* d_in, const int* in_sizes, int n_in,
                              void* d_out, int out_size) {
    const float* X = reinterpret_cast<const float*>(d_in[0]);
    float*       O = reinterpret_cast<float*>(d_out);
    cov_fused_kernel<<<BATCH * 2, THREADS>>>(X, O);
}